// round 5
// baseline (speedup 1.0000x reference)
#include <cuda_runtime.h>
#include <stdint.h>

#define THREADS 256
#define SPB 128
#define NE 30
#define HPAD 68          // sH row stride
#define EBS 2176         // expert buffer stride (floats)

typedef unsigned long long u64;

// ---- smem layout (floats) ----
#define OFF_W0   0                       // 384
#define OFF_B0   384                     // 128
#define OFF_B1   512                     // 64
#define OFF_W1   576                     // 8192 -> 8768
#define OFF_H    8768                    // 128*68 = 8704 -> 17472
#define OFF_EB   17472                   // 2*2176 = 4352 -> 21824
#define OFF_INT  21824                   // ints: 128+128+31+32+31 = 350
#define SMEM_FLOATS (OFF_INT + 352)
#define SMEM_BYTES  (SMEM_FLOATS * 4)    // 88704 B -> 2 CTAs/SM

// ---------- packed f32x2 helpers ----------
__device__ __forceinline__ u64 pk2(float lo, float hi) {
    u64 r; asm("mov.b64 %0,{%1,%2};" : "=l"(r) : "f"(lo), "f"(hi)); return r;
}
__device__ __forceinline__ void upk2(u64 v, float& lo, float& hi) {
    asm("mov.b64 {%0,%1},%2;" : "=f"(lo), "=f"(hi) : "l"(v));
}
__device__ __forceinline__ u64 fma2v(u64 a, u64 b, u64 c) {
    u64 d; asm("fma.rn.f32x2 %0,%1,%2,%3;" : "=l"(d) : "l"(a), "l"(b), "l"(c)); return d;
}
__device__ __forceinline__ void fma2acc(u64& d, u64 a, u64 b) {
    asm("fma.rn.f32x2 %0,%1,%2,%0;" : "+l"(d) : "l"(a), "l"(b));
}
__device__ __forceinline__ u64 mul2v(u64 a, u64 b) {
    u64 d; asm("mul.rn.f32x2 %0,%1,%2;" : "=l"(d) : "l"(a), "l"(b)); return d;
}

__device__ __forceinline__ float fast_rcp(float d) {
    float r = __int_as_float(0x7EF311C3 - __float_as_int(d));
    r = r * (2.0f - d * r);
    r = r * (2.0f - d * r);
    return r;
}

// packed pair tanh, Pade[7/6], FMA-pipe only
__device__ __forceinline__ float2 tanh2(float a, float b) {
    a = fminf(fmaxf(a, -5.0f), 5.0f);
    b = fminf(fmaxf(b, -5.0f), 5.0f);
    u64 cc = pk2(a, b);
    u64 uu = mul2v(cc, cc);
    u64 p = fma2v(uu, pk2(7.3996004e-6f, 7.3996004e-6f), pk2(2.7972028e-3f, 2.7972028e-3f));
    p = fma2v(uu, p, pk2(0.12820513f, 0.12820513f));
    p = fma2v(uu, p, pk2(1.0f, 1.0f));
    p = mul2v(p, cc);
    u64 q = fma2v(uu, pk2(2.0718881e-4f, 2.0718881e-4f), pk2(0.023310023f, 0.023310023f));
    q = fma2v(uu, q, pk2(0.46153846f, 0.46153846f));
    q = fma2v(uu, q, pk2(1.0f, 1.0f));
    float q0, q1; upk2(q, q0, q1);
    float r0 = __int_as_float(0x7EF311C3 - __float_as_int(q0));
    float r1 = __int_as_float(0x7EF311C3 - __float_as_int(q1));
    u64 rr = pk2(r0, r1);
    u64 nq = mul2v(q, pk2(-1.0f, -1.0f));
    u64 two = pk2(2.0f, 2.0f);
    rr = mul2v(rr, fma2v(nq, rr, two));
    rr = mul2v(rr, fma2v(nq, rr, two));
    u64 res = mul2v(p, rr);
    float o0, o1; upk2(res, o0, o1);
    return make_float2(o0, o1);
}

extern __shared__ float smem[];

__global__ __launch_bounds__(THREADS, 2)
void wfc_fused_kernel(const float* __restrict__ x,
                      const int* __restrict__ nn,
                      const int* __restrict__ ll,
                      const int* __restrict__ mm,
                      const float* __restrict__ W0, const float* __restrict__ b0,
                      const float* __restrict__ W1, const float* __restrict__ b1,
                      const float* __restrict__ Wa, const float* __restrict__ ba,
                      const float* __restrict__ Wb, const float* __restrict__ bb,
                      float* __restrict__ out, int B)
{
    float* sW0 = smem + OFF_W0;
    float* sb0 = smem + OFF_B0;
    float* sb1 = smem + OFF_B1;
    float* sW1 = smem + OFF_W1;
    float* sH  = smem + OFF_H;
    int* sEid    = (int*)(smem + OFF_INT);
    int* sPerm   = sEid + 128;
    int* sCnt    = sPerm + 128;     // 31 bins (bin 30 = inactive)
    int* sStart  = sCnt + 31;
    int* sCursor = sStart + 32;

    const int t = threadIdx.x;
    const int base = blockIdx.x * SPB;

    // ---- stage trunk weights ----
    for (int i = t; i < 384;  i += THREADS) sW0[i] = W0[i];
    if (t < 128) sb0[t] = b0[t];
    #pragma unroll
    for (int i = 0; i < 8; i++) ((float4*)sW1)[t + 256 * i] = ((const float4*)W1)[t + 256 * i];
    if (t < 64) sb1[t] = b1[t];
    if (t < 31) sCnt[t] = 0;
    __syncthreads();

    // ---- trunk: 2 threads per sample, 32 outputs each ----
    const int sl = t & 127;
    const int kbase = (t >> 7) << 5;     // 0 or 32
    const int s = base + sl;
    const bool active = (s < B);
    float x0 = 0.f, x1 = 0.f, x2 = 0.f;
    int eid = NE;
    if (active) {
        x0 = x[3 * s + 0];
        x1 = x[3 * s + 1];
        x2 = x[3 * s + 2];
        int n = nn[s], l = ll[s], m = mm[s];
        eid = ((n - 1) * n * (2 * n - 1)) / 6 + l * l + l + m;
    }
    if (t < 128) {
        sEid[t] = eid;
        atomicAdd(&sCnt[eid], 1);
    }

    const u64 xx0 = pk2(x0, x0);
    const u64 xx1 = pk2(x1, x1);
    const u64 xx2 = pk2(x2, x2);

    u64 acc2[16];
    {
        const ulonglong2* bsrc = (const ulonglong2*)(sb1 + kbase);
        #pragma unroll
        for (int q = 0; q < 8; q++) { ulonglong2 v = bsrc[q]; acc2[2*q] = v.x; acc2[2*q+1] = v.y; }
    }

    #pragma unroll 2
    for (int j = 0; j < 128; j += 2) {
        float2 wa2 = *(const float2*)(sW0 + j);
        float2 wb2 = *(const float2*)(sW0 + 128 + j);
        float2 wc2 = *(const float2*)(sW0 + 256 + j);
        float2 bp2 = *(const float2*)(sb0 + j);
        u64 pre2 = fma2v(xx0, pk2(wa2.x, wa2.y),
                   fma2v(xx1, pk2(wb2.x, wb2.y),
                   fma2v(xx2, pk2(wc2.x, wc2.y), pk2(bp2.x, bp2.y))));
        float p0, p1; upk2(pre2, p0, p1);
        float2 h = tanh2(p0, p1);
        u64 hh0 = pk2(h.x, h.x);
        u64 hh1 = pk2(h.y, h.y);
        const ulonglong2* wr0 = (const ulonglong2*)(sW1 + j * 64 + kbase);
        const ulonglong2* wr1 = (const ulonglong2*)(sW1 + (j + 1) * 64 + kbase);
        #pragma unroll
        for (int q = 0; q < 8; q++) {        // FIX: q<8 (all 32 outputs), was q<4
            ulonglong2 v0 = wr0[q];
            fma2acc(acc2[2*q],     hh0, v0.x);
            fma2acc(acc2[2*q + 1], hh0, v0.y);
        }
        #pragma unroll
        for (int q = 0; q < 8; q++) {        // FIX: q<8
            ulonglong2 v1 = wr1[q];
            fma2acc(acc2[2*q],     hh1, v1.x);
            fma2acc(acc2[2*q + 1], hh1, v1.y);
        }
    }

    // h1 = tanh(acc) -> sH
    {
        float* hrow = sH + sl * HPAD + kbase;
        #pragma unroll
        for (int q = 0; q < 4; q++) {
            float a, b, c, d;
            upk2(acc2[4*q],     a, b);
            upk2(acc2[4*q + 1], c, d);
            float2 t01 = tanh2(a, b);
            float2 t23 = tanh2(c, d);
            ((float4*)hrow)[2*q] = make_float4(t01.x, t01.y, t23.x, t23.y);
            upk2(acc2[4*q + 2], a, b);
            upk2(acc2[4*q + 3], c, d);
            t01 = tanh2(a, b);
            t23 = tanh2(c, d);
            ((float4*)hrow)[2*q + 1] = make_float4(t01.x, t01.y, t23.x, t23.y);
        }
    }
    __syncthreads();                 // counts + sH visible

    if (t == 0) {
        int run = 0;
        #pragma unroll
        for (int e = 0; e <= NE; e++) { sStart[e] = run; sCursor[e] = run; run += sCnt[e]; }
    }
    __syncthreads();                 // scan visible
    if (t < 128) {
        int pos = atomicAdd(&sCursor[eid], 1);
        sPerm[pos] = t;              // ordered by first in-loop barrier below
    }

    // ================= expert heads: skip-empty, double-buffered =================
    const int warp = t >> 5;
    const int lane = t & 31;
    const int dd = t >> 2;           // Wa row this thread stages (0..63)
    const int kb = (t & 3) * 8;      // 8 cols per thread
    const int dh = dd >> 1, dp = dd & 1;

    // find first non-empty expert; prefetch it
    int e = 0;
    while (e < NE && sStart[e + 1] == sStart[e]) e++;
    float4 wr0f, wr1f; float ext = 0.f;
    if (e < NE) {
        const float4* src = (const float4*)(Wa + e * 2048);
        wr0f = src[2 * t];
        wr1f = src[2 * t + 1];
        if (t < 32)       ext = ba[e * 32 + t];
        else if (t < 96)  ext = Wb[e * 64 + (t - 32)];
        else if (t < 98)  ext = bb[e * 2 + (t - 96)];
    }

    int parity = 0;
    while (e < NE) {
        float* buf = smem + OFF_EB + parity * EBS;
        // stage expert e from prefetched regs (interleaved j-pair layout)
        {
            float* wdst = buf + dh * 64 + dp;
            wdst[(kb + 0) * 2] = wr0f.x;
            wdst[(kb + 1) * 2] = wr0f.y;
            wdst[(kb + 2) * 2] = wr0f.z;
            wdst[(kb + 3) * 2] = wr0f.w;
            wdst[(kb + 4) * 2] = wr1f.x;
            wdst[(kb + 5) * 2] = wr1f.y;
            wdst[(kb + 6) * 2] = wr1f.z;
            wdst[(kb + 7) * 2] = wr1f.w;
            if (t < 32)       buf[2048 + t] = ext;
            else if (t < 96)  buf[2080 + (t - 32)] = ext;
            else if (t < 98)  buf[2144 + (t - 96)] = ext;
        }
        // next non-empty expert; prefetch it
        int en_ = e + 1;
        while (en_ < NE && sStart[en_ + 1] == sStart[en_]) en_++;
        if (en_ < NE) {
            const float4* src = (const float4*)(Wa + en_ * 2048);
            wr0f = src[2 * t];
            wr1f = src[2 * t + 1];
            if (t < 32)       ext = ba[en_ * 32 + t];
            else if (t < 96)  ext = Wb[en_ * 64 + (t - 32)];
            else if (t < 98)  ext = bb[en_ * 2 + (t - 96)];
        }
        __syncthreads();   // stage-e visible; also orders sPerm/sH on first iter

        const int st = sStart[e];
        const int en = sStart[e + 1];
        for (int i = st + 4 * warp; i < en; i += 32) {
            const int i1 = (i + 1 < en) ? i + 1 : i;
            const int i2 = (i + 2 < en) ? i + 2 : i;
            const int i3 = (i + 3 < en) ? i + 3 : i;
            const int p0i = sPerm[i],  p1i = sPerm[i1];
            const int p2i = sPerm[i2], p3i = sPerm[i3];
            const float* h0p = sH + p0i * HPAD;
            const float* h1p = sH + p1i * HPAD;
            const float* h2p = sH + p2i * HPAD;
            const float* h3p = sH + p3i * HPAD;
            u64 g0 = 0, g1 = 0, g2 = 0, g3 = 0;
            const float* wap = buf + lane * 2;
            #pragma unroll 8
            for (int r = 0; r < 32; r++) {
                u64 wv = *(const u64*)(wap);
                fma2acc(g0, *(const u64*)(h0p + 2*r), wv);
                fma2acc(g1, *(const u64*)(h1p + 2*r), wv);
                fma2acc(g2, *(const u64*)(h2p + 2*r), wv);
                fma2acc(g3, *(const u64*)(h3p + 2*r), wv);
                wap += 64;
            }
            const float bal = buf[2048 + lane];
            float a, b;
            upk2(g0, a, b); float G0 = (a + b) + bal;
            upk2(g1, a, b); float G1 = (a + b) + bal;
            upk2(g2, a, b); float G2 = (a + b) + bal;
            upk2(g3, a, b); float G3 = (a + b) + bal;
            float2 t01 = tanh2(G0, G1);
            float2 t23 = tanh2(G2, G3);
            const u64 wb2 = *(const u64*)(buf + 2080 + lane * 2);
            u64 pp0 = mul2v(pk2(t01.x, t01.x), wb2);
            u64 pp1 = mul2v(pk2(t01.y, t01.y), wb2);
            u64 pp2 = mul2v(pk2(t23.x, t23.x), wb2);
            u64 pp3 = mul2v(pk2(t23.y, t23.y), wb2);
            float q0a, q0b, q1a, q1b, q2a, q2b, q3a, q3b;
            upk2(pp0, q0a, q0b); upk2(pp1, q1a, q1b);
            upk2(pp2, q2a, q2b); upk2(pp3, q3a, q3b);
            #pragma unroll
            for (int off = 16; off > 0; off >>= 1) {
                q0a += __shfl_xor_sync(0xffffffffu, q0a, off);
                q0b += __shfl_xor_sync(0xffffffffu, q0b, off);
                q1a += __shfl_xor_sync(0xffffffffu, q1a, off);
                q1b += __shfl_xor_sync(0xffffffffu, q1b, off);
                q2a += __shfl_xor_sync(0xffffffffu, q2a, off);
                q2b += __shfl_xor_sync(0xffffffffu, q2b, off);
                q3a += __shfl_xor_sync(0xffffffffu, q3a, off);
                q3b += __shfl_xor_sync(0xffffffffu, q3b, off);
            }
            if (lane == 0) {
                const float bb0 = buf[2144], bb1 = buf[2145];
                float u0 = q0a + bb0, v0 = q0b + bb1;
                float u1 = q1a + bb0, v1 = q1b + bb1;
                float u2 = q2a + bb0, v2 = q2b + bb1;
                float u3 = q3a + bb0, v3 = q3b + bb1;
                float r0 = rsqrtf(fmaf(u0, u0, fmaf(v0, v0, 1e-6f)));
                float r1 = rsqrtf(fmaf(u1, u1, fmaf(v1, v1, 1e-6f)));
                float r2 = rsqrtf(fmaf(u2, u2, fmaf(v2, v2, 1e-6f)));
                float r3 = rsqrtf(fmaf(u3, u3, fmaf(v3, v3, 1e-6f)));
                ((float2*)out)[base + p0i] = make_float2(u0 * r0, v0 * r0);
                if (i + 1 < en) ((float2*)out)[base + p1i] = make_float2(u1 * r1, v1 * r1);
                if (i + 2 < en) ((float2*)out)[base + p2i] = make_float2(u2 * r2, v2 * r2);
                if (i + 3 < en) ((float2*)out)[base + p3i] = make_float2(u3 * r3, v3 * r3);
            }
        }
        e = en_;
        parity ^= 1;
    }
}

extern "C" void kernel_launch(void* const* d_in, const int* in_sizes, int n_in,
                              void* d_out, int out_size) {
    const float* x  = (const float*)d_in[0];
    const int*   nn = (const int*)  d_in[1];
    const int*   ll = (const int*)  d_in[2];
    const int*   mm = (const int*)  d_in[3];
    const float* W0 = (const float*)d_in[4];
    const float* b0 = (const float*)d_in[5];
    const float* W1 = (const float*)d_in[6];
    const float* b1 = (const float*)d_in[7];
    const float* Wa = (const float*)d_in[8];
    const float* ba = (const float*)d_in[9];
    const float* Wb = (const float*)d_in[10];
    const float* bb = (const float*)d_in[11];
    float* out = (float*)d_out;

    const int B = in_sizes[1];
    const int blocks = (B + SPB - 1) / SPB;

    cudaFuncSetAttribute(wfc_fused_kernel,
                         cudaFuncAttributeMaxDynamicSharedMemorySize, SMEM_BYTES);
    wfc_fused_kernel<<<blocks, THREADS, SMEM_BYTES>>>(
        x, nn, ll, mm, W0, b0, W1, b1, Wa, ba, Wb, bb, out, B);
}

// round 6
// speedup vs baseline: 1.0851x; 1.0851x over previous
#include <cuda_runtime.h>
#include <stdint.h>

#define THREADS 256
#define SPB 128
#define NE 30
#define HPAD 68          // sH row stride (floats)
#define H0S 132          // h0T row stride (floats, multiple of 4)
#define EBS 2176         // expert buffer stride (floats)

typedef unsigned long long u64;

// ---- smem layout (floats) ----
#define OFF_W0   0                       // 384
#define OFF_B0   384                     // 128
#define OFF_B1   512                     // 64
#define OFF_W1   576                     // 8192 -> 8768
#define OFF_EB   576                     // ALIAS: expert bufs (2*2176=4352) live in dead W1
#define OFF_H0T  8768                    // 128*132 = 16896 -> 25664
#define OFF_H    8768                    // ALIAS: sH (128*68=8704) lives in dead h0T
#define OFF_INT  25664                   // ints: 128(perm)+31+32+31 = 222 -> 224
#define SMEM_FLOATS (OFF_INT + 224)
#define SMEM_BYTES  (SMEM_FLOATS * 4)    // 103552 B -> 2 CTAs/SM

// ---------- packed f32x2 helpers ----------
__device__ __forceinline__ u64 pk2(float lo, float hi) {
    u64 r; asm("mov.b64 %0,{%1,%2};" : "=l"(r) : "f"(lo), "f"(hi)); return r;
}
__device__ __forceinline__ void upk2(u64 v, float& lo, float& hi) {
    asm("mov.b64 {%0,%1},%2;" : "=f"(lo), "=f"(hi) : "l"(v));
}
__device__ __forceinline__ u64 fma2v(u64 a, u64 b, u64 c) {
    u64 d; asm("fma.rn.f32x2 %0,%1,%2,%3;" : "=l"(d) : "l"(a), "l"(b), "l"(c)); return d;
}
__device__ __forceinline__ void fma2acc(u64& d, u64 a, u64 b) {
    asm("fma.rn.f32x2 %0,%1,%2,%0;" : "+l"(d) : "l"(a), "l"(b));
}
__device__ __forceinline__ u64 mul2v(u64 a, u64 b) {
    u64 d; asm("mul.rn.f32x2 %0,%1,%2;" : "=l"(d) : "l"(a), "l"(b)); return d;
}

// packed pair tanh, Pade[7/6], FMA-pipe only (no MUFU)
__device__ __forceinline__ float2 tanh2(float a, float b) {
    a = fminf(fmaxf(a, -5.0f), 5.0f);
    b = fminf(fmaxf(b, -5.0f), 5.0f);
    u64 cc = pk2(a, b);
    u64 uu = mul2v(cc, cc);
    u64 p = fma2v(uu, pk2(7.3996004e-6f, 7.3996004e-6f), pk2(2.7972028e-3f, 2.7972028e-3f));
    p = fma2v(uu, p, pk2(0.12820513f, 0.12820513f));
    p = fma2v(uu, p, pk2(1.0f, 1.0f));
    p = mul2v(p, cc);
    u64 q = fma2v(uu, pk2(2.0718881e-4f, 2.0718881e-4f), pk2(0.023310023f, 0.023310023f));
    q = fma2v(uu, q, pk2(0.46153846f, 0.46153846f));
    q = fma2v(uu, q, pk2(1.0f, 1.0f));
    float q0, q1; upk2(q, q0, q1);
    float r0 = __int_as_float(0x7EF311C3 - __float_as_int(q0));
    float r1 = __int_as_float(0x7EF311C3 - __float_as_int(q1));
    u64 rr = pk2(r0, r1);
    u64 nq = mul2v(q, pk2(-1.0f, -1.0f));
    u64 two = pk2(2.0f, 2.0f);
    rr = mul2v(rr, fma2v(nq, rr, two));
    rr = mul2v(rr, fma2v(nq, rr, two));
    u64 res = mul2v(p, rr);
    float o0, o1; upk2(res, o0, o1);
    return make_float2(o0, o1);
}

extern __shared__ float smem[];

__global__ __launch_bounds__(THREADS, 2)
void wfc_fused_kernel(const float* __restrict__ x,
                      const int* __restrict__ nn,
                      const int* __restrict__ ll,
                      const int* __restrict__ mm,
                      const float* __restrict__ W0, const float* __restrict__ b0,
                      const float* __restrict__ W1, const float* __restrict__ b1,
                      const float* __restrict__ Wa, const float* __restrict__ ba,
                      const float* __restrict__ Wb, const float* __restrict__ bb,
                      float* __restrict__ out, int B)
{
    float* sW0  = smem + OFF_W0;
    float* sb0  = smem + OFF_B0;
    float* sb1  = smem + OFF_B1;
    float* sW1  = smem + OFF_W1;
    float* sH0T = smem + OFF_H0T;
    float* sH   = smem + OFF_H;     // alias of h0T region (bar-separated)
    int* sPerm   = (int*)(smem + OFF_INT);
    int* sCnt    = sPerm + 128;     // 31 bins (bin 30 = inactive)
    int* sStart  = sCnt + 31;       // 32
    int* sCursor = sStart + 32;     // 31

    const int t = threadIdx.x;
    const int base = blockIdx.x * SPB;

    // ---- stage trunk weights ----
    for (int i = t; i < 384;  i += THREADS) sW0[i] = W0[i];
    if (t < 128) sb0[t] = b0[t];
    #pragma unroll
    for (int i = 0; i < 8; i++) ((float4*)sW1)[t + 256 * i] = ((const float4*)W1)[t + 256 * i];
    if (t < 64) sb1[t] = b1[t];
    if (t < 31) sCnt[t] = 0;
    __syncthreads();                                       // bar0

    // ================= PASS A: h0=tanh(x@W0+b0) -> h0T[j][s] (2 thr/sample) =====
    const int sa = t & 127;
    const int ubase = (t >> 7) * 64;       // units 0..63 or 64..127
    const int s = base + sa;
    const bool active = (s < B);
    float x0 = 0.f, x1 = 0.f, x2 = 0.f;
    int eid = NE;
    if (active) {
        x0 = x[3 * s + 0];
        x1 = x[3 * s + 1];
        x2 = x[3 * s + 2];
    }
    if (t < 128) {
        if (active) {
            int n = nn[s], l = ll[s], m = mm[s];
            eid = ((n - 1) * n * (2 * n - 1)) / 6 + l * l + l + m;
        }
        atomicAdd(&sCnt[eid], 1);
    }
    {
        const u64 xx0 = pk2(x0, x0);
        const u64 xx1 = pk2(x1, x1);
        const u64 xx2 = pk2(x2, x2);
        float* hdst = sH0T + ubase * H0S + sa;
        #pragma unroll 8
        for (int up = 0; up < 32; up++) {
            const int u = ubase + 2 * up;
            float2 wa2 = *(const float2*)(sW0 + u);
            float2 wb2 = *(const float2*)(sW0 + 128 + u);
            float2 wc2 = *(const float2*)(sW0 + 256 + u);
            float2 bp2 = *(const float2*)(sb0 + u);
            u64 pre = fma2v(xx0, pk2(wa2.x, wa2.y),
                      fma2v(xx1, pk2(wb2.x, wb2.y),
                      fma2v(xx2, pk2(wc2.x, wc2.y), pk2(bp2.x, bp2.y))));
            float p0, p1; upk2(pre, p0, p1);
            float2 h = tanh2(p0, p1);
            hdst[0]   = h.x;
            hdst[H0S] = h.y;
            hdst += 2 * H0S;
        }
    }
    __syncthreads();                                       // bar1: h0T + counts

    if (t == 0) {          // tiny scan, overlapped with pass B of other threads
        int run = 0;
        #pragma unroll
        for (int e = 0; e <= NE; e++) { sStart[e] = run; sCursor[e] = run; run += sCnt[e]; }
    }

    // ================= PASS B: C[128x64]=h0T@W1, 4 samples x 8 outputs/thread ====
    const int sg = t & 31;           // sample group: samples 4sg..4sg+3
    const int og = t >> 5;           // output group: outputs 8og..8og+7
    u64 acc[16];                     // [s4][op] : 4 samples x 4 u64 (8 outputs)
    {
        const ulonglong2* bi = (const ulonglong2*)(sb1 + og * 8);
        ulonglong2 b01 = bi[0], b23 = bi[1];
        #pragma unroll
        for (int s4 = 0; s4 < 4; s4++) {
            acc[s4 * 4 + 0] = b01.x; acc[s4 * 4 + 1] = b01.y;
            acc[s4 * 4 + 2] = b23.x; acc[s4 * 4 + 3] = b23.y;
        }
    }
    {
        const float* hrow = sH0T + 4 * sg;
        const float* wrow = sW1 + og * 8;
        #pragma unroll 4
        for (int j = 0; j < 128; j++) {
            float4 h4 = *(const float4*)(hrow + j * H0S);
            ulonglong2 wv0 = *(const ulonglong2*)(wrow + j * 64);
            ulonglong2 wv1 = *(const ulonglong2*)(wrow + j * 64 + 4);
            u64 hh;
            hh = pk2(h4.x, h4.x);
            fma2acc(acc[0],  hh, wv0.x); fma2acc(acc[1],  hh, wv0.y);
            fma2acc(acc[2],  hh, wv1.x); fma2acc(acc[3],  hh, wv1.y);
            hh = pk2(h4.y, h4.y);
            fma2acc(acc[4],  hh, wv0.x); fma2acc(acc[5],  hh, wv0.y);
            fma2acc(acc[6],  hh, wv1.x); fma2acc(acc[7],  hh, wv1.y);
            hh = pk2(h4.z, h4.z);
            fma2acc(acc[8],  hh, wv0.x); fma2acc(acc[9],  hh, wv0.y);
            fma2acc(acc[10], hh, wv1.x); fma2acc(acc[11], hh, wv1.y);
            hh = pk2(h4.w, h4.w);
            fma2acc(acc[12], hh, wv0.x); fma2acc(acc[13], hh, wv0.y);
            fma2acc(acc[14], hh, wv1.x); fma2acc(acc[15], hh, wv1.y);
        }
    }
    __syncthreads();                                       // bar2: all h0T reads done

    // scatter by expert (scan done by t0 before bar2)
    if (t < 128) {
        int pos = atomicAdd(&sCursor[eid], 1);
        sPerm[pos] = t;              // ordered by first in-loop barrier below
    }
    // epilogue: tanh -> sH (overwrites h0T region; safe after bar2)
    {
        #pragma unroll
        for (int s4 = 0; s4 < 4; s4++) {
            float* hr = sH + (4 * sg + s4) * HPAD + og * 8;
            float a, b, c, d;
            upk2(acc[s4 * 4 + 0], a, b);
            upk2(acc[s4 * 4 + 1], c, d);
            float2 t01 = tanh2(a, b);
            float2 t23 = tanh2(c, d);
            ((float4*)hr)[0] = make_float4(t01.x, t01.y, t23.x, t23.y);
            upk2(acc[s4 * 4 + 2], a, b);
            upk2(acc[s4 * 4 + 3], c, d);
            t01 = tanh2(a, b);
            t23 = tanh2(c, d);
            ((float4*)hr)[1] = make_float4(t01.x, t01.y, t23.x, t23.y);
        }
    }

    // ================= PHASE 3: expert heads (skip-empty, double-buffered) ======
    const int warp = t >> 5;
    const int lane = t & 31;
    const int dd = t >> 2;           // Wa row this thread stages (0..63)
    const int kb = (t & 3) * 8;      // 8 cols per thread
    const int dh = dd >> 1, dp = dd & 1;

    int e = 0;
    while (e < NE && sStart[e + 1] == sStart[e]) e++;
    float4 wr0f, wr1f; float ext = 0.f;
    if (e < NE) {
        const float4* src = (const float4*)(Wa + e * 2048);
        wr0f = src[2 * t];
        wr1f = src[2 * t + 1];
        if (t < 32)       ext = ba[e * 32 + t];
        else if (t < 96)  ext = Wb[e * 64 + (t - 32)];
        else if (t < 98)  ext = bb[e * 2 + (t - 96)];
    }

    int parity = 0;
    while (e < NE) {
        float* buf = smem + OFF_EB + parity * EBS;   // lives in dead W1 region
        {
            float* wdst = buf + dh * 64 + dp;
            wdst[(kb + 0) * 2] = wr0f.x;
            wdst[(kb + 1) * 2] = wr0f.y;
            wdst[(kb + 2) * 2] = wr0f.z;
            wdst[(kb + 3) * 2] = wr0f.w;
            wdst[(kb + 4) * 2] = wr1f.x;
            wdst[(kb + 5) * 2] = wr1f.y;
            wdst[(kb + 6) * 2] = wr1f.z;
            wdst[(kb + 7) * 2] = wr1f.w;
            if (t < 32)       buf[2048 + t] = ext;
            else if (t < 96)  buf[2080 + (t - 32)] = ext;
            else if (t < 98)  buf[2144 + (t - 96)] = ext;
        }
        int en_ = e + 1;
        while (en_ < NE && sStart[en_ + 1] == sStart[en_]) en_++;
        if (en_ < NE) {
            const float4* src = (const float4*)(Wa + en_ * 2048);
            wr0f = src[2 * t];
            wr1f = src[2 * t + 1];
            if (t < 32)       ext = ba[en_ * 32 + t];
            else if (t < 96)  ext = Wb[en_ * 64 + (t - 32)];
            else if (t < 98)  ext = bb[en_ * 2 + (t - 96)];
        }
        __syncthreads();   // stage-e visible; orders sPerm/sH on first iter

        const int st = sStart[e];
        const int en = sStart[e + 1];
        for (int i = st + 4 * warp; i < en; i += 32) {
            const int i1 = (i + 1 < en) ? i + 1 : i;
            const int i2 = (i + 2 < en) ? i + 2 : i;
            const int i3 = (i + 3 < en) ? i + 3 : i;
            const int p0i = sPerm[i],  p1i = sPerm[i1];
            const int p2i = sPerm[i2], p3i = sPerm[i3];
            const float* h0p = sH + p0i * HPAD;
            const float* h1p = sH + p1i * HPAD;
            const float* h2p = sH + p2i * HPAD;
            const float* h3p = sH + p3i * HPAD;
            u64 g0 = 0, g1 = 0, g2 = 0, g3 = 0;
            const float* wap = buf + lane * 2;
            #pragma unroll 8
            for (int r = 0; r < 32; r++) {
                u64 wv = *(const u64*)(wap);
                fma2acc(g0, *(const u64*)(h0p + 2*r), wv);
                fma2acc(g1, *(const u64*)(h1p + 2*r), wv);
                fma2acc(g2, *(const u64*)(h2p + 2*r), wv);
                fma2acc(g3, *(const u64*)(h3p + 2*r), wv);
                wap += 64;
            }
            const float bal = buf[2048 + lane];
            float a, b;
            upk2(g0, a, b); float G0 = (a + b) + bal;
            upk2(g1, a, b); float G1 = (a + b) + bal;
            upk2(g2, a, b); float G2 = (a + b) + bal;
            upk2(g3, a, b); float G3 = (a + b) + bal;
            float2 t01 = tanh2(G0, G1);
            float2 t23 = tanh2(G2, G3);
            const u64 wb2 = *(const u64*)(buf + 2080 + lane * 2);
            u64 pp0 = mul2v(pk2(t01.x, t01.x), wb2);
            u64 pp1 = mul2v(pk2(t01.y, t01.y), wb2);
            u64 pp2 = mul2v(pk2(t23.x, t23.x), wb2);
            u64 pp3 = mul2v(pk2(t23.y, t23.y), wb2);
            float q0a, q0b, q1a, q1b, q2a, q2b, q3a, q3b;
            upk2(pp0, q0a, q0b); upk2(pp1, q1a, q1b);
            upk2(pp2, q2a, q2b); upk2(pp3, q3a, q3b);
            #pragma unroll
            for (int off = 16; off > 0; off >>= 1) {
                q0a += __shfl_xor_sync(0xffffffffu, q0a, off);
                q0b += __shfl_xor_sync(0xffffffffu, q0b, off);
                q1a += __shfl_xor_sync(0xffffffffu, q1a, off);
                q1b += __shfl_xor_sync(0xffffffffu, q1b, off);
                q2a += __shfl_xor_sync(0xffffffffu, q2a, off);
                q2b += __shfl_xor_sync(0xffffffffu, q2b, off);
                q3a += __shfl_xor_sync(0xffffffffu, q3a, off);
                q3b += __shfl_xor_sync(0xffffffffu, q3b, off);
            }
            if (lane == 0) {
                const float bb0 = buf[2144], bb1 = buf[2145];
                float u0 = q0a + bb0, v0 = q0b + bb1;
                float u1 = q1a + bb0, v1 = q1b + bb1;
                float u2 = q2a + bb0, v2 = q2b + bb1;
                float u3 = q3a + bb0, v3 = q3b + bb1;
                float r0 = rsqrtf(fmaf(u0, u0, fmaf(v0, v0, 1e-6f)));
                float r1 = rsqrtf(fmaf(u1, u1, fmaf(v1, v1, 1e-6f)));
                float r2 = rsqrtf(fmaf(u2, u2, fmaf(v2, v2, 1e-6f)));
                float r3 = rsqrtf(fmaf(u3, u3, fmaf(v3, v3, 1e-6f)));
                ((float2*)out)[base + p0i] = make_float2(u0 * r0, v0 * r0);
                if (i + 1 < en) ((float2*)out)[base + p1i] = make_float2(u1 * r1, v1 * r1);
                if (i + 2 < en) ((float2*)out)[base + p2i] = make_float2(u2 * r2, v2 * r2);
                if (i + 3 < en) ((float2*)out)[base + p3i] = make_float2(u3 * r3, v3 * r3);
            }
        }
        e = en_;
        parity ^= 1;
    }
}

extern "C" void kernel_launch(void* const* d_in, const int* in_sizes, int n_in,
                              void* d_out, int out_size) {
    const float* x  = (const float*)d_in[0];
    const int*   nn = (const int*)  d_in[1];
    const int*   ll = (const int*)  d_in[2];
    const int*   mm = (const int*)  d_in[3];
    const float* W0 = (const float*)d_in[4];
    const float* b0 = (const float*)d_in[5];
    const float* W1 = (const float*)d_in[6];
    const float* b1 = (const float*)d_in[7];
    const float* Wa = (const float*)d_in[8];
    const float* ba = (const float*)d_in[9];
    const float* Wb = (const float*)d_in[10];
    const float* bb = (const float*)d_in[11];
    float* out = (float*)d_out;

    const int B = in_sizes[1];
    const int blocks = (B + SPB - 1) / SPB;

    cudaFuncSetAttribute(wfc_fused_kernel,
                         cudaFuncAttributeMaxDynamicSharedMemorySize, SMEM_BYTES);
    wfc_fused_kernel<<<blocks, THREADS, SMEM_BYTES>>>(
        x, nn, ll, mm, W0, b0, W1, b1, Wa, ba, Wb, bb, out, B);
}

// round 7
// speedup vs baseline: 1.8352x; 1.6913x over previous
#include <cuda_runtime.h>
#include <stdint.h>

#define MAXB 262144
#define TSPB 128            // trunk samples per block
#define ESPB 256            // expert samples per block
#define NE 30
#define H0S 132             // h0T row stride (floats)
#define NDESC_MAX (MAXB / ESPB + NE + 2)

typedef unsigned long long u64;

// ---------------- device scratch (allocation-free) ----------------
__device__ float g_h[MAXB * 64];
__device__ int   g_eid[MAXB];
__device__ int   g_perm[MAXB];
__device__ int   g_cnt[32];
__device__ int   g_cursor[32];
__device__ int   g_desc_e[NDESC_MAX];
__device__ int   g_desc_s[NDESC_MAX];
__device__ int   g_desc_c[NDESC_MAX];
__device__ int   g_ndesc;

// ---------------- packed f32x2 helpers ----------------
__device__ __forceinline__ u64 pk2(float lo, float hi) {
    u64 r; asm("mov.b64 %0,{%1,%2};" : "=l"(r) : "f"(lo), "f"(hi)); return r;
}
__device__ __forceinline__ void upk2(u64 v, float& lo, float& hi) {
    asm("mov.b64 {%0,%1},%2;" : "=f"(lo), "=f"(hi) : "l"(v));
}
__device__ __forceinline__ u64 fma2v(u64 a, u64 b, u64 c) {
    u64 d; asm("fma.rn.f32x2 %0,%1,%2,%3;" : "=l"(d) : "l"(a), "l"(b), "l"(c)); return d;
}
__device__ __forceinline__ void fma2acc(u64& d, u64 a, u64 b) {
    asm("fma.rn.f32x2 %0,%1,%2,%0;" : "+l"(d) : "l"(a), "l"(b));
}
__device__ __forceinline__ u64 mul2v(u64 a, u64 b) {
    u64 d; asm("mul.rn.f32x2 %0,%1,%2;" : "=l"(d) : "l"(a), "l"(b)); return d;
}

// packed pair tanh, Pade[7/6], FMA-pipe only (no MUFU)
__device__ __forceinline__ float2 tanh2(float a, float b) {
    a = fminf(fmaxf(a, -5.0f), 5.0f);
    b = fminf(fmaxf(b, -5.0f), 5.0f);
    u64 cc = pk2(a, b);
    u64 uu = mul2v(cc, cc);
    u64 p = fma2v(uu, pk2(7.3996004e-6f, 7.3996004e-6f), pk2(2.7972028e-3f, 2.7972028e-3f));
    p = fma2v(uu, p, pk2(0.12820513f, 0.12820513f));
    p = fma2v(uu, p, pk2(1.0f, 1.0f));
    p = mul2v(p, cc);
    u64 q = fma2v(uu, pk2(2.0718881e-4f, 2.0718881e-4f), pk2(0.023310023f, 0.023310023f));
    q = fma2v(uu, q, pk2(0.46153846f, 0.46153846f));
    q = fma2v(uu, q, pk2(1.0f, 1.0f));
    float q0, q1; upk2(q, q0, q1);
    float r0 = __int_as_float(0x7EF311C3 - __float_as_int(q0));
    float r1 = __int_as_float(0x7EF311C3 - __float_as_int(q1));
    u64 rr = pk2(r0, r1);
    u64 nq = mul2v(q, pk2(-1.0f, -1.0f));
    u64 two = pk2(2.0f, 2.0f);
    rr = mul2v(rr, fma2v(nq, rr, two));
    rr = mul2v(rr, fma2v(nq, rr, two));
    u64 res = mul2v(p, rr);
    float o0, o1; upk2(res, o0, o1);
    return make_float2(o0, o1);
}

// ================= K0: init histogram =================
__global__ void init_kernel() {
    if (threadIdx.x < 32) g_cnt[threadIdx.x] = 0;
}

// ================= K1: trunk (h -> global) + eid + histogram =================
// smem: W0 384 | b0 128 | b1 64 | W1 8192 | h0T 128*H0S | sCnt 32
#define T_OFF_W0  0
#define T_OFF_B0  384
#define T_OFF_B1  512
#define T_OFF_W1  576
#define T_OFF_H0T 8768
#define T_OFF_INT (8768 + 128 * H0S)         // 25664
#define T_SMEM_FLOATS (T_OFF_INT + 32)
#define T_SMEM_BYTES  (T_SMEM_FLOATS * 4)    // ~102.8 KB -> 2 CTAs/SM

extern __shared__ float smem[];

__global__ __launch_bounds__(256, 2)
void trunk_kernel(const float* __restrict__ x,
                  const int* __restrict__ nn,
                  const int* __restrict__ ll,
                  const int* __restrict__ mm,
                  const float* __restrict__ W0, const float* __restrict__ b0,
                  const float* __restrict__ W1, const float* __restrict__ b1,
                  int B)
{
    float* sW0  = smem + T_OFF_W0;
    float* sb0  = smem + T_OFF_B0;
    float* sb1  = smem + T_OFF_B1;
    float* sW1  = smem + T_OFF_W1;
    float* sH0T = smem + T_OFF_H0T;
    int*   sCnt = (int*)(smem + T_OFF_INT);

    const int t = threadIdx.x;
    const int base = blockIdx.x * TSPB;

    for (int i = t; i < 384; i += 256) sW0[i] = W0[i];
    if (t < 128) sb0[t] = b0[t];
    #pragma unroll
    for (int i = 0; i < 8; i++) ((float4*)sW1)[t + 256 * i] = ((const float4*)W1)[t + 256 * i];
    if (t < 64) sb1[t] = b1[t];
    if (t < 31) sCnt[t] = 0;
    __syncthreads();

    // ---- pass A: h0 = tanh(x@W0+b0) -> h0T[j][s], 2 threads/sample ----
    const int sa = t & 127;
    const int ubase = (t >> 7) * 64;
    const int s = base + sa;
    const bool active = (s < B);
    float x0 = 0.f, x1 = 0.f, x2 = 0.f;
    if (active) {
        x0 = x[3 * s + 0];
        x1 = x[3 * s + 1];
        x2 = x[3 * s + 2];
    }
    if (t < 128) {
        int eid = NE;
        if (active) {
            int n = nn[s], l = ll[s], m = mm[s];
            eid = ((n - 1) * n * (2 * n - 1)) / 6 + l * l + l + m;
            g_eid[s] = eid;
        }
        if (eid < NE) atomicAdd(&sCnt[eid], 1);
    }
    {
        const u64 xx0 = pk2(x0, x0);
        const u64 xx1 = pk2(x1, x1);
        const u64 xx2 = pk2(x2, x2);
        float* hdst = sH0T + ubase * H0S + sa;
        #pragma unroll 8
        for (int up = 0; up < 32; up++) {
            const int u = ubase + 2 * up;
            float2 wa2 = *(const float2*)(sW0 + u);
            float2 wb2 = *(const float2*)(sW0 + 128 + u);
            float2 wc2 = *(const float2*)(sW0 + 256 + u);
            float2 bp2 = *(const float2*)(sb0 + u);
            u64 pre = fma2v(xx0, pk2(wa2.x, wa2.y),
                      fma2v(xx1, pk2(wb2.x, wb2.y),
                      fma2v(xx2, pk2(wc2.x, wc2.y), pk2(bp2.x, bp2.y))));
            float p0, p1; upk2(pre, p0, p1);
            float2 h = tanh2(p0, p1);
            hdst[0]   = h.x;
            hdst[H0S] = h.y;
            hdst += 2 * H0S;
        }
    }
    __syncthreads();

    if (t < 30) {
        int c = sCnt[t];
        if (c) atomicAdd(&g_cnt[t], c);
    }

    // ---- pass B: C[128x64] = h0T @ W1 ; og=t&7 (8 outs), sg=t>>3 (4 samples) ----
    const int og = t & 7;
    const int sg = t >> 3;
    u64 acc[16];
    {
        const ulonglong2* bi = (const ulonglong2*)(sb1 + og * 8);
        ulonglong2 b01 = bi[0], b23 = bi[1];
        #pragma unroll
        for (int s4 = 0; s4 < 4; s4++) {
            acc[s4 * 4 + 0] = b01.x; acc[s4 * 4 + 1] = b01.y;
            acc[s4 * 4 + 2] = b23.x; acc[s4 * 4 + 3] = b23.y;
        }
    }
    {
        const float* hrow = sH0T + 4 * sg;
        const float* wrow = sW1 + og * 8;
        #pragma unroll 4
        for (int j = 0; j < 128; j++) {
            float4 h4 = *(const float4*)(hrow + j * H0S);
            ulonglong2 wv0 = *(const ulonglong2*)(wrow + j * 64);
            ulonglong2 wv1 = *(const ulonglong2*)(wrow + j * 64 + 4);
            u64 hh;
            hh = pk2(h4.x, h4.x);
            fma2acc(acc[0],  hh, wv0.x); fma2acc(acc[1],  hh, wv0.y);
            fma2acc(acc[2],  hh, wv1.x); fma2acc(acc[3],  hh, wv1.y);
            hh = pk2(h4.y, h4.y);
            fma2acc(acc[4],  hh, wv0.x); fma2acc(acc[5],  hh, wv0.y);
            fma2acc(acc[6],  hh, wv1.x); fma2acc(acc[7],  hh, wv1.y);
            hh = pk2(h4.z, h4.z);
            fma2acc(acc[8],  hh, wv0.x); fma2acc(acc[9],  hh, wv0.y);
            fma2acc(acc[10], hh, wv1.x); fma2acc(acc[11], hh, wv1.y);
            hh = pk2(h4.w, h4.w);
            fma2acc(acc[12], hh, wv0.x); fma2acc(acc[13], hh, wv0.y);
            fma2acc(acc[14], hh, wv1.x); fma2acc(acc[15], hh, wv1.y);
        }
    }
    // epilogue: tanh -> g_h[s][64] (coalesced across og)
    #pragma unroll
    for (int s4 = 0; s4 < 4; s4++) {
        const int row = 4 * sg + s4;
        const int sg_ = base + row;
        if (sg_ < B) {
            float a, b, c, d;
            upk2(acc[s4 * 4 + 0], a, b);
            upk2(acc[s4 * 4 + 1], c, d);
            float2 t01 = tanh2(a, b);
            float2 t23 = tanh2(c, d);
            float* hr = g_h + sg_ * 64 + og * 8;
            ((float4*)hr)[0] = make_float4(t01.x, t01.y, t23.x, t23.y);
            upk2(acc[s4 * 4 + 2], a, b);
            upk2(acc[s4 * 4 + 3], c, d);
            t01 = tanh2(a, b);
            t23 = tanh2(c, d);
            ((float4*)hr)[1] = make_float4(t01.x, t01.y, t23.x, t23.y);
        }
    }
}

// ================= K2: scan + descriptors =================
__global__ void scan_kernel() {
    __shared__ int sStart[NE], sNb[NE], sDb[NE];
    const int t = threadIdx.x;
    if (t == 0) {
        int run = 0, nd = 0;
        for (int e = 0; e < NE; e++) {
            sStart[e] = run;
            int c = g_cnt[e];
            int nb = (c + ESPB - 1) / ESPB;
            sNb[e] = nb;
            sDb[e] = nd;
            nd += nb;
            run += c;
        }
        g_ndesc = nd;
    }
    __syncthreads();
    if (t < NE) {
        g_cursor[t] = sStart[t];
        const int nb = sNb[t], db = sDb[t], st = sStart[t], c = g_cnt[t];
        for (int b = 0; b < nb; b++) {
            g_desc_e[db + b] = t;
            g_desc_s[db + b] = st + b * ESPB;
            int rem = c - b * ESPB;
            g_desc_c[db + b] = rem < ESPB ? rem : ESPB;
        }
    }
}

// ================= K3: scatter into sorted perm =================
__global__ __launch_bounds__(256)
void scatter_kernel(int B) {
    __shared__ int sCnt[32], sRes[32];
    const int t = threadIdx.x;
    const int s = blockIdx.x * 256 + t;
    if (t < 32) sCnt[t] = 0;
    __syncthreads();
    int eid = 31;
    int myloc = 0;
    if (s < B) {
        eid = g_eid[s];
        myloc = atomicAdd(&sCnt[eid], 1);
    }
    __syncthreads();
    if (t < NE) {
        int c = sCnt[t];
        sRes[t] = c ? atomicAdd(&g_cursor[t], c) : 0;
    }
    __syncthreads();
    if (s < B && eid < NE) g_perm[sRes[eid] + myloc] = s;
}

// ================= K4: expert heads, thread-per-sample =================
// smem floats: Wa[2048] | ba[32] | wb0[32] | wb1[32] | bb[2]
__global__ __launch_bounds__(256)
void expert_kernel(const float* __restrict__ Wa, const float* __restrict__ ba,
                   const float* __restrict__ Wb, const float* __restrict__ bb,
                   float* __restrict__ out)
{
    __shared__ float sWa[2048];
    __shared__ float sba[32], sWb0[32], sWb1[32], sbb[2];

    const int bid = blockIdx.x;
    if (bid >= g_ndesc) return;
    const int t = threadIdx.x;
    const int e   = g_desc_e[bid];
    const int st  = g_desc_s[bid];
    const int cnt = g_desc_c[bid];

    ((float4*)sWa)[t]       = ((const float4*)(Wa + e * 2048))[t];
    ((float4*)sWa)[t + 256] = ((const float4*)(Wa + e * 2048))[t + 256];
    if (t < 32) {
        sba[t]  = ba[e * 32 + t];
        sWb0[t] = Wb[e * 64 + 2 * t];
        sWb1[t] = Wb[e * 64 + 2 * t + 1];
    }
    if (t < 2) sbb[t] = bb[e * 2 + t];
    __syncthreads();

    const bool valid = (t < cnt);
    const int s = g_perm[st + (valid ? t : 0)];
    const float* hp = g_h + s * 64;

    u64 g2[16];
    #pragma unroll
    for (int q = 0; q < 16; q++) g2[q] = *(const u64*)(sba + 2 * q);

    #pragma unroll 4
    for (int j2 = 0; j2 < 32; j2++) {
        u64 hpair = *(const u64*)(hp + 2 * j2);
        float h0, h1; upk2(hpair, h0, h1);
        u64 hh0 = pk2(h0, h0);
        u64 hh1 = pk2(h1, h1);
        const ulonglong2* w0 = (const ulonglong2*)(sWa + (2 * j2) * 32);
        const ulonglong2* w1 = (const ulonglong2*)(sWa + (2 * j2 + 1) * 32);
        #pragma unroll
        for (int q = 0; q < 8; q++) {
            ulonglong2 wv0 = w0[q];
            fma2acc(g2[2 * q],     hh0, wv0.x);
            fma2acc(g2[2 * q + 1], hh0, wv0.y);
        }
        #pragma unroll
        for (int q = 0; q < 8; q++) {
            ulonglong2 wv1 = w1[q];
            fma2acc(g2[2 * q],     hh1, wv1.x);
            fma2acc(g2[2 * q + 1], hh1, wv1.y);
        }
    }

    // G = tanh(g); psi = G @ Wb + bb; normalize
    u64 P0 = 0, P1 = 0;
    #pragma unroll
    for (int q = 0; q < 16; q++) {
        float a, b; upk2(g2[q], a, b);
        float2 tg = tanh2(a, b);
        u64 G = pk2(tg.x, tg.y);
        fma2acc(P0, G, *(const u64*)(sWb0 + 2 * q));
        fma2acc(P1, G, *(const u64*)(sWb1 + 2 * q));
    }
    float a0, b0_, a1, b1_;
    upk2(P0, a0, b0_);
    upk2(P1, a1, b1_);
    float p0 = a0 + b0_ + sbb[0];
    float p1 = a1 + b1_ + sbb[1];
    float r = rsqrtf(fmaf(p0, p0, fmaf(p1, p1, 1e-6f)));
    if (valid) ((float2*)out)[s] = make_float2(p0 * r, p1 * r);
}

// ================= host =================
extern "C" void kernel_launch(void* const* d_in, const int* in_sizes, int n_in,
                              void* d_out, int out_size) {
    const float* x  = (const float*)d_in[0];
    const int*   nn = (const int*)  d_in[1];
    const int*   ll = (const int*)  d_in[2];
    const int*   mm = (const int*)  d_in[3];
    const float* W0 = (const float*)d_in[4];
    const float* b0 = (const float*)d_in[5];
    const float* W1 = (const float*)d_in[6];
    const float* b1 = (const float*)d_in[7];
    const float* Wa = (const float*)d_in[8];
    const float* ba = (const float*)d_in[9];
    const float* Wb = (const float*)d_in[10];
    const float* bb = (const float*)d_in[11];
    float* out = (float*)d_out;

    const int B = in_sizes[1];

    static int trunk_attr_set = 0;
    if (!trunk_attr_set) {
        cudaFuncSetAttribute(trunk_kernel,
                             cudaFuncAttributeMaxDynamicSharedMemorySize, T_SMEM_BYTES);
        trunk_attr_set = 1;
    }

    init_kernel<<<1, 32>>>();
    trunk_kernel<<<(B + TSPB - 1) / TSPB, 256, T_SMEM_BYTES>>>(
        x, nn, ll, mm, W0, b0, W1, b1, B);
    scan_kernel<<<1, 32>>>();
    scatter_kernel<<<(B + 255) / 256, 256>>>(B);
    expert_kernel<<<(B + ESPB - 1) / ESPB + NE, 256>>>(Wa, ba, Wb, bb, out);
}

// round 8
// speedup vs baseline: 1.9851x; 1.0817x over previous
#include <cuda_runtime.h>
#include <stdint.h>

#define MAXB 262144
#define TSPB 128            // trunk samples per block
#define ESPB 256            // expert samples per block
#define NE 30
#define H0S 132             // h0T row stride (floats)
#define NDESC_MAX (MAXB / ESPB + NE + 2)

typedef unsigned long long u64;

// ---------------- device scratch (allocation-free) ----------------
__device__ float g_h[MAXB * 64];
__device__ int   g_eid[MAXB];
__device__ int   g_perm[MAXB];
__device__ int   g_cnt[32];
__device__ int   g_cursor[32];
__device__ int   g_desc_e[NDESC_MAX];
__device__ int   g_desc_s[NDESC_MAX];
__device__ int   g_desc_c[NDESC_MAX];
__device__ int   g_ndesc;

// ---------------- packed f32x2 helpers ----------------
__device__ __forceinline__ u64 pk2(float lo, float hi) {
    u64 r; asm("mov.b64 %0,{%1,%2};" : "=l"(r) : "f"(lo), "f"(hi)); return r;
}
__device__ __forceinline__ void upk2(u64 v, float& lo, float& hi) {
    asm("mov.b64 {%0,%1},%2;" : "=f"(lo), "=f"(hi) : "l"(v));
}
__device__ __forceinline__ u64 fma2v(u64 a, u64 b, u64 c) {
    u64 d; asm("fma.rn.f32x2 %0,%1,%2,%3;" : "=l"(d) : "l"(a), "l"(b), "l"(c)); return d;
}
__device__ __forceinline__ void fma2acc(u64& d, u64 a, u64 b) {
    asm("fma.rn.f32x2 %0,%1,%2,%0;" : "+l"(d) : "l"(a), "l"(b));
}
__device__ __forceinline__ u64 mul2v(u64 a, u64 b) {
    u64 d; asm("mul.rn.f32x2 %0,%1,%2;" : "=l"(d) : "l"(a), "l"(b)); return d;
}

// packed pair tanh, Pade[7/6], FMA-pipe only (no MUFU)
__device__ __forceinline__ float2 tanh2(float a, float b) {
    a = fminf(fmaxf(a, -5.0f), 5.0f);
    b = fminf(fmaxf(b, -5.0f), 5.0f);
    u64 cc = pk2(a, b);
    u64 uu = mul2v(cc, cc);
    u64 p = fma2v(uu, pk2(7.3996004e-6f, 7.3996004e-6f), pk2(2.7972028e-3f, 2.7972028e-3f));
    p = fma2v(uu, p, pk2(0.12820513f, 0.12820513f));
    p = fma2v(uu, p, pk2(1.0f, 1.0f));
    p = mul2v(p, cc);
    u64 q = fma2v(uu, pk2(2.0718881e-4f, 2.0718881e-4f), pk2(0.023310023f, 0.023310023f));
    q = fma2v(uu, q, pk2(0.46153846f, 0.46153846f));
    q = fma2v(uu, q, pk2(1.0f, 1.0f));
    float q0, q1; upk2(q, q0, q1);
    float r0 = __int_as_float(0x7EF311C3 - __float_as_int(q0));
    float r1 = __int_as_float(0x7EF311C3 - __float_as_int(q1));
    u64 rr = pk2(r0, r1);
    u64 nq = mul2v(q, pk2(-1.0f, -1.0f));
    u64 two = pk2(2.0f, 2.0f);
    rr = mul2v(rr, fma2v(nq, rr, two));
    rr = mul2v(rr, fma2v(nq, rr, two));
    u64 res = mul2v(p, rr);
    float o0, o1; upk2(res, o0, o1);
    return make_float2(o0, o1);
}

// ================= K0: init histogram =================
__global__ void init_kernel() {
    if (threadIdx.x < 32) g_cnt[threadIdx.x] = 0;
}

// ================= K1: trunk (h -> global) + eid + histogram =================
#define T_OFF_W0  0
#define T_OFF_B0  384
#define T_OFF_B1  512
#define T_OFF_W1  576
#define T_OFF_H0T 8768
#define T_OFF_INT (8768 + 128 * H0S)
#define T_SMEM_FLOATS (T_OFF_INT + 32)
#define T_SMEM_BYTES  (T_SMEM_FLOATS * 4)    // ~102.8 KB -> 2 CTAs/SM

extern __shared__ float smem[];

__global__ __launch_bounds__(256, 2)
void trunk_kernel(const float* __restrict__ x,
                  const int* __restrict__ nn,
                  const int* __restrict__ ll,
                  const int* __restrict__ mm,
                  const float* __restrict__ W0, const float* __restrict__ b0,
                  const float* __restrict__ W1, const float* __restrict__ b1,
                  int B)
{
    float* sW0  = smem + T_OFF_W0;
    float* sb0  = smem + T_OFF_B0;
    float* sb1  = smem + T_OFF_B1;
    float* sW1  = smem + T_OFF_W1;
    float* sH0T = smem + T_OFF_H0T;
    int*   sCnt = (int*)(smem + T_OFF_INT);

    const int t = threadIdx.x;
    const int base = blockIdx.x * TSPB;

    for (int i = t; i < 384; i += 256) sW0[i] = W0[i];
    if (t < 128) sb0[t] = b0[t];
    #pragma unroll
    for (int i = 0; i < 8; i++) ((float4*)sW1)[t + 256 * i] = ((const float4*)W1)[t + 256 * i];
    if (t < 64) sb1[t] = b1[t];
    if (t < 31) sCnt[t] = 0;
    __syncthreads();

    // ---- pass A: h0 = tanh(x@W0+b0) -> h0T[j][s], 2 threads/sample ----
    const int sa = t & 127;
    const int ubase = (t >> 7) * 64;
    const int s = base + sa;
    const bool active = (s < B);
    float x0 = 0.f, x1 = 0.f, x2 = 0.f;
    if (active) {
        x0 = x[3 * s + 0];
        x1 = x[3 * s + 1];
        x2 = x[3 * s + 2];
    }
    if (t < 128) {
        int eid = NE;
        if (active) {
            int n = nn[s], l = ll[s], m = mm[s];
            eid = ((n - 1) * n * (2 * n - 1)) / 6 + l * l + l + m;
            g_eid[s] = eid;
        }
        if (eid < NE) atomicAdd(&sCnt[eid], 1);
    }
    {
        const u64 xx0 = pk2(x0, x0);
        const u64 xx1 = pk2(x1, x1);
        const u64 xx2 = pk2(x2, x2);
        float* hdst = sH0T + ubase * H0S + sa;
        #pragma unroll 8
        for (int up = 0; up < 32; up++) {
            const int u = ubase + 2 * up;
            float2 wa2 = *(const float2*)(sW0 + u);
            float2 wb2 = *(const float2*)(sW0 + 128 + u);
            float2 wc2 = *(const float2*)(sW0 + 256 + u);
            float2 bp2 = *(const float2*)(sb0 + u);
            u64 pre = fma2v(xx0, pk2(wa2.x, wa2.y),
                      fma2v(xx1, pk2(wb2.x, wb2.y),
                      fma2v(xx2, pk2(wc2.x, wc2.y), pk2(bp2.x, bp2.y))));
            float p0, p1; upk2(pre, p0, p1);
            float2 h = tanh2(p0, p1);
            hdst[0]   = h.x;
            hdst[H0S] = h.y;
            hdst += 2 * H0S;
        }
    }
    __syncthreads();

    if (t < 30) {
        int c = sCnt[t];
        if (c) atomicAdd(&g_cnt[t], c);
    }

    // ---- pass B: C[128x64] = h0T @ W1 ; og=t&7 (8 outs), sg=t>>3 (4 samples) ----
    const int og = t & 7;
    const int sg = t >> 3;
    u64 acc[16];
    {
        const ulonglong2* bi = (const ulonglong2*)(sb1 + og * 8);
        ulonglong2 b01 = bi[0], b23 = bi[1];
        #pragma unroll
        for (int s4 = 0; s4 < 4; s4++) {
            acc[s4 * 4 + 0] = b01.x; acc[s4 * 4 + 1] = b01.y;
            acc[s4 * 4 + 2] = b23.x; acc[s4 * 4 + 3] = b23.y;
        }
    }
    {
        const float* hrow = sH0T + 4 * sg;
        const float* wrow = sW1 + og * 8;
        #pragma unroll 4
        for (int j = 0; j < 128; j++) {
            float4 h4 = *(const float4*)(hrow + j * H0S);
            ulonglong2 wv0 = *(const ulonglong2*)(wrow + j * 64);
            ulonglong2 wv1 = *(const ulonglong2*)(wrow + j * 64 + 4);
            u64 hh;
            hh = pk2(h4.x, h4.x);
            fma2acc(acc[0],  hh, wv0.x); fma2acc(acc[1],  hh, wv0.y);
            fma2acc(acc[2],  hh, wv1.x); fma2acc(acc[3],  hh, wv1.y);
            hh = pk2(h4.y, h4.y);
            fma2acc(acc[4],  hh, wv0.x); fma2acc(acc[5],  hh, wv0.y);
            fma2acc(acc[6],  hh, wv1.x); fma2acc(acc[7],  hh, wv1.y);
            hh = pk2(h4.z, h4.z);
            fma2acc(acc[8],  hh, wv0.x); fma2acc(acc[9],  hh, wv0.y);
            fma2acc(acc[10], hh, wv1.x); fma2acc(acc[11], hh, wv1.y);
            hh = pk2(h4.w, h4.w);
            fma2acc(acc[12], hh, wv0.x); fma2acc(acc[13], hh, wv0.y);
            fma2acc(acc[14], hh, wv1.x); fma2acc(acc[15], hh, wv1.y);
        }
    }
    // epilogue: tanh -> g_h[s][64] (coalesced across og)
    #pragma unroll
    for (int s4 = 0; s4 < 4; s4++) {
        const int row = 4 * sg + s4;
        const int sg_ = base + row;
        if (sg_ < B) {
            float a, b, c, d;
            upk2(acc[s4 * 4 + 0], a, b);
            upk2(acc[s4 * 4 + 1], c, d);
            float2 t01 = tanh2(a, b);
            float2 t23 = tanh2(c, d);
            float* hr = g_h + sg_ * 64 + og * 8;
            ((float4*)hr)[0] = make_float4(t01.x, t01.y, t23.x, t23.y);
            upk2(acc[s4 * 4 + 2], a, b);
            upk2(acc[s4 * 4 + 3], c, d);
            t01 = tanh2(a, b);
            t23 = tanh2(c, d);
            ((float4*)hr)[1] = make_float4(t01.x, t01.y, t23.x, t23.y);
        }
    }
}

// ================= K2: scan + descriptors =================
__global__ void scan_kernel() {
    __shared__ int sStart[NE], sNb[NE], sDb[NE];
    const int t = threadIdx.x;
    if (t == 0) {
        int run = 0, nd = 0;
        for (int e = 0; e < NE; e++) {
            sStart[e] = run;
            int c = g_cnt[e];
            int nb = (c + ESPB - 1) / ESPB;
            sNb[e] = nb;
            sDb[e] = nd;
            nd += nb;
            run += c;
        }
        g_ndesc = nd;
    }
    __syncthreads();
    if (t < NE) {
        g_cursor[t] = sStart[t];
        const int nb = sNb[t], db = sDb[t], st = sStart[t], c = g_cnt[t];
        for (int b = 0; b < nb; b++) {
            g_desc_e[db + b] = t;
            g_desc_s[db + b] = st + b * ESPB;
            int rem = c - b * ESPB;
            g_desc_c[db + b] = rem < ESPB ? rem : ESPB;
        }
    }
}

// ================= K3: scatter into sorted perm =================
__global__ __launch_bounds__(256)
void scatter_kernel(int B) {
    __shared__ int sCnt[32], sRes[32];
    const int t = threadIdx.x;
    const int s = blockIdx.x * 256 + t;
    if (t < 32) sCnt[t] = 0;
    __syncthreads();
    int eid = 31;
    int myloc = 0;
    if (s < B) {
        eid = g_eid[s];
        myloc = atomicAdd(&sCnt[eid], 1);
    }
    __syncthreads();
    if (t < NE) {
        int c = sCnt[t];
        sRes[t] = c ? atomicAdd(&g_cursor[t], c) : 0;
    }
    __syncthreads();
    if (s < B && eid < NE) g_perm[sRes[eid] + myloc] = s;
}

// ================= K4: expert heads, thread-per-sample, pipelined h loads ======
// smem floats: Wa[2048] | ba[32] | wb0[32] | wb1[32] | bb[2]
__global__ __launch_bounds__(256)
void expert_kernel(const float* __restrict__ Wa, const float* __restrict__ ba,
                   const float* __restrict__ Wb, const float* __restrict__ bb,
                   float* __restrict__ out)
{
    __shared__ float sWa[2048];
    __shared__ float sba[32], sWb0[32], sWb1[32], sbb[2];

    const int bid = blockIdx.x;
    if (bid >= g_ndesc) return;
    const int t = threadIdx.x;
    const int e   = g_desc_e[bid];
    const int st  = g_desc_s[bid];
    const int cnt = g_desc_c[bid];

    const bool valid = (t < cnt);
    const int s = g_perm[st + (valid ? t : 0)];
    const float4* hp4 = (const float4*)(g_h + s * 64);

    // issue the first two h loads before staging (latency overlaps staging+bar)
    float4 hcur = hp4[0];
    float4 hnxt = hp4[1];

    ((float4*)sWa)[t]       = ((const float4*)(Wa + e * 2048))[t];
    ((float4*)sWa)[t + 256] = ((const float4*)(Wa + e * 2048))[t + 256];
    if (t < 32) {
        sba[t]  = ba[e * 32 + t];
        sWb0[t] = Wb[e * 64 + 2 * t];
        sWb1[t] = Wb[e * 64 + 2 * t + 1];
    }
    if (t < 2) sbb[t] = bb[e * 2 + t];
    __syncthreads();

    u64 g2[16];
    #pragma unroll
    for (int q = 0; q < 16; q++) g2[q] = *(const u64*)(sba + 2 * q);

    // 16 float4 chunks of h; depth-1 software pipeline on the global loads
    #pragma unroll
    for (int q = 0; q < 16; q++) {
        float4 h4 = hcur;
        hcur = hnxt;
        if (q < 14) hnxt = hp4[q + 2];
        const int j0 = 4 * q;
        u64 hh;
        const ulonglong2* w;
        hh = pk2(h4.x, h4.x);
        w = (const ulonglong2*)(sWa + (j0 + 0) * 32);
        #pragma unroll
        for (int r = 0; r < 8; r++) { ulonglong2 wv = w[r]; fma2acc(g2[2*r], hh, wv.x); fma2acc(g2[2*r+1], hh, wv.y); }
        hh = pk2(h4.y, h4.y);
        w = (const ulonglong2*)(sWa + (j0 + 1) * 32);
        #pragma unroll
        for (int r = 0; r < 8; r++) { ulonglong2 wv = w[r]; fma2acc(g2[2*r], hh, wv.x); fma2acc(g2[2*r+1], hh, wv.y); }
        hh = pk2(h4.z, h4.z);
        w = (const ulonglong2*)(sWa + (j0 + 2) * 32);
        #pragma unroll
        for (int r = 0; r < 8; r++) { ulonglong2 wv = w[r]; fma2acc(g2[2*r], hh, wv.x); fma2acc(g2[2*r+1], hh, wv.y); }
        hh = pk2(h4.w, h4.w);
        w = (const ulonglong2*)(sWa + (j0 + 3) * 32);
        #pragma unroll
        for (int r = 0; r < 8; r++) { ulonglong2 wv = w[r]; fma2acc(g2[2*r], hh, wv.x); fma2acc(g2[2*r+1], hh, wv.y); }
    }

    // G = tanh(g); psi = G @ Wb + bb; normalize
    u64 P0 = 0, P1 = 0;
    #pragma unroll
    for (int q = 0; q < 16; q++) {
        float a, b; upk2(g2[q], a, b);
        float2 tg = tanh2(a, b);
        u64 G = pk2(tg.x, tg.y);
        fma2acc(P0, G, *(const u64*)(sWb0 + 2 * q));
        fma2acc(P1, G, *(const u64*)(sWb1 + 2 * q));
    }
    float a0, b0_, a1, b1_;
    upk2(P0, a0, b0_);
    upk2(P1, a1, b1_);
    float p0 = a0 + b0_ + sbb[0];
    float p1 = a1 + b1_ + sbb[1];
    float r = rsqrtf(fmaf(p0, p0, fmaf(p1, p1, 1e-6f)));
    if (valid) ((float2*)out)[s] = make_float2(p0 * r, p1 * r);
}

// ================= host =================
extern "C" void kernel_launch(void* const* d_in, const int* in_sizes, int n_in,
                              void* d_out, int out_size) {
    const float* x  = (const float*)d_in[0];
    const int*   nn = (const int*)  d_in[1];
    const int*   ll = (const int*)  d_in[2];
    const int*   mm = (const int*)  d_in[3];
    const float* W0 = (const float*)d_in[4];
    const float* b0 = (const float*)d_in[5];
    const float* W1 = (const float*)d_in[6];
    const float* b1 = (const float*)d_in[7];
    const float* Wa = (const float*)d_in[8];
    const float* ba = (const float*)d_in[9];
    const float* Wb = (const float*)d_in[10];
    const float* bb = (const float*)d_in[11];
    float* out = (float*)d_out;

    const int B = in_sizes[1];

    static int trunk_attr_set = 0;
    if (!trunk_attr_set) {
        cudaFuncSetAttribute(trunk_kernel,
                             cudaFuncAttributeMaxDynamicSharedMemorySize, T_SMEM_BYTES);
        trunk_attr_set = 1;
    }

    init_kernel<<<1, 32>>>();
    trunk_kernel<<<(B + TSPB - 1) / TSPB, 256, T_SMEM_BYTES>>>(
        x, nn, ll, mm, W0, b0, W1, b1, B);
    scan_kernel<<<1, 32>>>();
    scatter_kernel<<<(B + 255) / 256, 256>>>(B);
    expert_kernel<<<(B + ESPB - 1) / ESPB + NE, 256>>>(Wa, ba, Wb, bb, out);
}